// round 1
// baseline (speedup 1.0000x reference)
#include <cuda_runtime.h>

#define W 8192
#define H 2048
#define NPIX (W * H)

// pitch = (1 - i/H) * (FOV_UP + |FOV_DOWN|) - |FOV_DOWN|
#define FOV_SPAN     0.5235987755982988f   // 30 deg in rad
#define FOV_ABS_DOWN 0.2617993877991494f   // 15 deg in rad
#define TWO_PI       6.283185307179586f
#define PI_F         3.141592653589793f

// Hot tables: yaw cos/sin per column (64 KB), sin(pitch) per row (8 KB).
static __device__ float2 g_cs_yaw[W];
static __device__ float  g_sin_pitch[H];

__global__ void fill_tables_kernel() {
    int t = blockIdx.x * blockDim.x + threadIdx.x;
    if (t < W) {
        // yaw = j / w * 2*pi - pi   (same f32 formulation as reference)
        float yaw = (float)t / (float)W * TWO_PI - PI_F;
        float s, c;
        sincosf(yaw, &s, &c);
        g_cs_yaw[t] = make_float2(c, s);
    }
    if (t < H) {
        float pitch = (1.0f - (float)t / (float)H) * FOV_SPAN - FOV_ABS_DOWN;
        g_sin_pitch[t] = sinf(pitch);
    }
}

// Each thread: 4 consecutive pixels of one row.
//   loads:  4 x float4 (64 B contiguous, depth = .w)
//   stores: 3 x float4 (48 B contiguous, byte offset 48*t -> 16B aligned)
__global__ void __launch_bounds__(256)
proj_to_pointcloud_kernel(const float4* __restrict__ img, float4* __restrict__ out) {
    int t = blockIdx.x * blockDim.x + threadIdx.x;
    int p = t << 2;              // base pixel index (multiple of 4, same row)
    int i = p >> 13;             // row    (p / 8192)
    int j = p & (W - 1);         // column (p % 8192)

    // Streaming loads: don't pollute L2 (keep it for the tables).
    float4 p0 = __ldcs(img + p);
    float4 p1 = __ldcs(img + p + 1);
    float4 p2 = __ldcs(img + p + 2);
    float4 p3 = __ldcs(img + p + 3);

    float sp   = g_sin_pitch[i];
    float2 cs0 = g_cs_yaw[j];
    float2 cs1 = g_cs_yaw[j + 1];
    float2 cs2 = g_cs_yaw[j + 2];
    float2 cs3 = g_cs_yaw[j + 3];

    float d0 = p0.w, d1 = p1.w, d2 = p2.w, d3 = p3.w;

    float x0 =  d0 * cs0.x, y0 = -d0 * cs0.y, z0 = d0 * sp;
    float x1 =  d1 * cs1.x, y1 = -d1 * cs1.y, z1 = d1 * sp;
    float x2 =  d2 * cs2.x, y2 = -d2 * cs2.y, z2 = d2 * sp;
    float x3 =  d3 * cs3.x, y3 = -d3 * cs3.y, z3 = d3 * sp;

    float4 o0 = make_float4(x0, y0, z0, x1);
    float4 o1 = make_float4(y1, z1, x2, y2);
    float4 o2 = make_float4(z2, x3, y3, z3);

    long ob = (long)t * 3;
    __stcs(out + ob,     o0);
    __stcs(out + ob + 1, o1);
    __stcs(out + ob + 2, o2);
}

extern "C" void kernel_launch(void* const* d_in, const int* in_sizes, int n_in,
                              void* d_out, int out_size) {
    const float4* img = (const float4*)d_in[0];
    float4* out = (float4*)d_out;

    // Prologue: fill yaw/pitch tables (tiny, ~32 blocks).
    fill_tables_kernel<<<(W + 255) / 256, 256>>>();

    // Main streaming kernel: NPIX/4 threads.
    int threads = 256;
    int total_threads = NPIX / 4;            // 4,194,304
    int blocks = total_threads / threads;    // 16,384
    proj_to_pointcloud_kernel<<<blocks, threads>>>(img, out);
}